// round 7
// baseline (speedup 1.0000x reference)
#include <cuda_runtime.h>
#include <cuda_bf16.h>
#include <cstdint>

#define B_    8
#define C_    256
#define N_    1024
#define NH    8
#define HD    32
#define R_    4
#define PR_   768          // q,k,v rows in proj
#define SCALE 0.17677669529663689f
#define LOG2E 1.4426950408889634f

// ---------------- scratch ----------------
__device__ float g_proj[B_ * PR_ * N_];
__device__ float g_sq[B_ * N_];
__device__ float g_sk[B_ * N_];
__device__ float g_ball[PR_];
__device__ __nv_bfloat16 g_whi[PR_ * C_], g_wlo[PR_ * C_];
__device__ __nv_bfloat16 g_wphi[C_ * C_], g_wplo[C_ * C_];
__device__ __nv_bfloat16 g_xhi[B_ * C_ * N_], g_xlo[B_ * C_ * N_];
__device__ __nv_bfloat16 g_qB[B_ * C_ * N_];   // gated*SCALE*LOG2E
__device__ __nv_bfloat16 g_kB[B_ * C_ * N_];   // gated
__device__ __nv_bfloat16 g_vB[B_ * C_ * N_];
__device__ __nv_bfloat16 g_ghi[B_ * C_ * N_], g_glo[B_ * C_ * N_];

// ---------------- ptx helpers ----------------
__device__ __forceinline__ void cp16(void* d, const void* s) {
    uint32_t ds = (uint32_t)__cvta_generic_to_shared(d);
    asm volatile("cp.async.cg.shared.global [%0], [%1], 16;" :: "r"(ds), "l"(s));
}
__device__ __forceinline__ void cp_commit() { asm volatile("cp.async.commit_group;"); }

__device__ __forceinline__ void ldsm_x4(uint32_t (&r)[4], const void* p) {
    uint32_t a = (uint32_t)__cvta_generic_to_shared(p);
    asm volatile("ldmatrix.sync.aligned.m8n8.x4.shared.b16 {%0,%1,%2,%3},[%4];"
                 : "=r"(r[0]), "=r"(r[1]), "=r"(r[2]), "=r"(r[3]) : "r"(a));
}
__device__ __forceinline__ void ldsm_x4t(uint32_t (&r)[4], const void* p) {
    uint32_t a = (uint32_t)__cvta_generic_to_shared(p);
    asm volatile("ldmatrix.sync.aligned.m8n8.x4.trans.shared.b16 {%0,%1,%2,%3},[%4];"
                 : "=r"(r[0]), "=r"(r[1]), "=r"(r[2]), "=r"(r[3]) : "r"(a));
}
__device__ __forceinline__ void ldsm_x2(uint32_t (&r)[2], const void* p) {
    uint32_t a = (uint32_t)__cvta_generic_to_shared(p);
    asm volatile("ldmatrix.sync.aligned.m8n8.x2.shared.b16 {%0,%1},[%2];"
                 : "=r"(r[0]), "=r"(r[1]) : "r"(a));
}
__device__ __forceinline__ void ldsm_x2t(uint32_t (&r)[2], const void* p) {
    uint32_t a = (uint32_t)__cvta_generic_to_shared(p);
    asm volatile("ldmatrix.sync.aligned.m8n8.x2.trans.shared.b16 {%0,%1},[%2];"
                 : "=r"(r[0]), "=r"(r[1]) : "r"(a));
}
__device__ __forceinline__ void mma16816(float (&d)[4], const uint32_t (&a)[4], const uint32_t (&b)[2]) {
    asm volatile(
        "mma.sync.aligned.m16n8k16.row.col.f32.bf16.bf16.f32 "
        "{%0,%1,%2,%3},{%4,%5,%6,%7},{%8,%9},{%0,%1,%2,%3};"
        : "+f"(d[0]), "+f"(d[1]), "+f"(d[2]), "+f"(d[3])
        : "r"(a[0]), "r"(a[1]), "r"(a[2]), "r"(a[3]), "r"(b[0]), "r"(b[1]));
}
__device__ __forceinline__ uint32_t packbf(float lo, float hi) {
    __nv_bfloat162 t = __floats2bfloat162_rn(lo, hi);
    return *reinterpret_cast<uint32_t*>(&t);
}
__device__ __forceinline__ float ex2(float x) {
    float y; asm("ex2.approx.ftz.f32 %0,%1;" : "=f"(y) : "f"(x)); return y;
}
__device__ __forceinline__ void split_bf(float x, __nv_bfloat16& hi, __nv_bfloat16& lo) {
    hi = __float2bfloat16_rn(x);
    lo = __float2bfloat16_rn(x - __bfloat162float(hi));
}

// ---------------- assemble + split weights (q,k,v + Wp) ----------------
__global__ void assemble_split_kernel(
    const float* __restrict__ Wq, const float* __restrict__ bq,
    const float* __restrict__ Wk, const float* __restrict__ bk,
    const float* __restrict__ Wv, const float* __restrict__ bv,
    const float* __restrict__ Wp)
{
    int o = blockIdx.x;
    int k = threadIdx.x;
    if (o < PR_) {
        const float* src; const float* bs; int r;
        if (o < 256)      { src = Wq  + o * 256;       bs = bq; r = o; }
        else if (o < 512) { src = Wk  + (o-256) * 256; bs = bk; r = o - 256; }
        else              { src = Wv  + (o-512) * 256; bs = bv; r = o - 512; }
        __nv_bfloat16 hi, lo; split_bf(src[k], hi, lo);
        g_whi[o * 256 + k] = hi; g_wlo[o * 256 + k] = lo;
        if (k == 0) g_ball[o] = bs[r];
    } else {
        int r = o - PR_;
        __nv_bfloat16 hi, lo; split_bf(Wp[r * 256 + k], hi, lo);
        g_wphi[r * 256 + k] = hi; g_wplo[r * 256 + k] = lo;
    }
}

// ---------------- split x into bf16 hi/lo (float4 vectorized) ----------------
__global__ void xsplit_kernel(const float* __restrict__ x) {
    int i = (blockIdx.x * 256 + threadIdx.x) * 4;
    float4 v = *reinterpret_cast<const float4*>(x + i);
    __nv_bfloat16 h0,l0,h1,l1,h2,l2,h3,l3;
    split_bf(v.x,h0,l0); split_bf(v.y,h1,l1); split_bf(v.z,h2,l2); split_bf(v.w,h3,l3);
    uint2 ph, pl;
    ph.x = ((uint32_t)*(uint16_t*)&h1 << 16) | *(uint16_t*)&h0;
    ph.y = ((uint32_t)*(uint16_t*)&h3 << 16) | *(uint16_t*)&h2;
    pl.x = ((uint32_t)*(uint16_t*)&l1 << 16) | *(uint16_t*)&l0;
    pl.y = ((uint32_t)*(uint16_t*)&l3 << 16) | *(uint16_t*)&l2;
    *reinterpret_cast<uint2*>(g_xhi + i) = ph;
    *reinterpret_cast<uint2*>(g_xlo + i) = pl;
}

// ---------------- fused gate projection + gumbel softmax (fp32, from x) ----------------
__global__ __launch_bounds__(128) void gateproj_kernel(
    const float* __restrict__ x, const float* __restrict__ gq, const float* __restrict__ gk,
    const float* __restrict__ Wsq, const float* __restrict__ bsq,
    const float* __restrict__ Wsk, const float* __restrict__ bsk)
{
    int b = blockIdx.y;
    int n = blockIdx.x * 128 + threadIdx.x;
    __shared__ float sw[8][256];
    for (int i = threadIdx.x; i < 2048; i += 128) {
        int r = i >> 8, c = i & 255;
        sw[r][c] = (r < 4) ? Wsq[r * 256 + c] : Wsk[(r - 4) * 256 + c];
    }
    __syncthreads();

    float acc[8];
    #pragma unroll
    for (int r = 0; r < 4; r++) { acc[r] = bsq[r]; acc[r + 4] = bsk[r]; }
    const float* xb = x + (long)b * C_ * N_ + n;
    #pragma unroll 4
    for (int c = 0; c < 256; c++) {
        float xv = xb[(long)c * N_];
        #pragma unroll
        for (int r = 0; r < 8; r++) acc[r] += sw[r][c] * xv;
    }
    float lq[4], lk[4];
    #pragma unroll
    for (int r = 0; r < 4; r++) {
        lq[r] = acc[r]     + gq[(b * R_ + r) * N_ + n];
        lk[r] = acc[r + 4] + gk[(b * R_ + r) * N_ + n];
    }
    float mq = fmaxf(fmaxf(lq[0], lq[1]), fmaxf(lq[2], lq[3]));
    float s = 0.f;
    #pragma unroll
    for (int r = 0; r < 4; r++) s += __expf(lq[r] - mq);
    g_sq[b * N_ + n] = __expf(lq[0] - mq) / s;
    float mk = fmaxf(fmaxf(lk[0], lk[1]), fmaxf(lk[2], lk[3]));
    s = 0.f;
    #pragma unroll
    for (int r = 0; r < 4; r++) s += __expf(lk[r] - mk);
    g_sk[b * N_ + n] = __expf(lk[0] - mk) / s;
}

// ---------------- bf16x3 GEMM (M multiple of 128, no masking) ----------------
__global__ __launch_bounds__(256) void gemm3x_kernel(
    const __nv_bfloat16* __restrict__ Whi, const __nv_bfloat16* __restrict__ Wlo,
    const float* __restrict__ bias,
    const __nv_bfloat16* __restrict__ Xhi, const __nv_bfloat16* __restrict__ Xlo,
    float* __restrict__ Y, long xStride, long yStride)
{
    int b  = blockIdx.z;
    int m0 = blockIdx.y * 128;
    int n0 = blockIdx.x * 128;
    const __nv_bfloat16* XhiB = Xhi + (long)b * xStride;
    const __nv_bfloat16* XloB = Xlo + (long)b * xStride;

    __shared__ __align__(16) __nv_bfloat16 sA[2][2][128 * 16];
    __shared__ __align__(16) __nv_bfloat16 sB[2][2][16 * 136];

    int tid  = threadIdx.x;
    int warp = tid >> 5, lane = tid & 31;
    int wm = warp >> 2, wn = warp & 3;
    int g = lane >> 2, t = lane & 3;

    float acc[4][4][4];
    #pragma unroll
    for (int mi = 0; mi < 4; mi++)
        #pragma unroll
        for (int ni = 0; ni < 4; ni++)
            #pragma unroll
            for (int r = 0; r < 4; r++) acc[mi][ni][r] = 0.f;

    auto loadStage = [&](int step, int s) {
        int k0 = step * 16;
        {
            int row = tid >> 1, half = tid & 1;
            int gm = m0 + row;
            cp16(&sA[s][0][row * 16 + half * 8], Whi + gm * 256 + k0 + half * 8);
            cp16(&sA[s][1][row * 16 + half * 8], Wlo + gm * 256 + k0 + half * 8);
        }
        {
            int row = tid >> 4, seg = tid & 15;
            cp16(&sB[s][0][row * 136 + seg * 8], XhiB + (long)(k0 + row) * N_ + n0 + seg * 8);
            cp16(&sB[s][1][row * 136 + seg * 8], XloB + (long)(k0 + row) * N_ + n0 + seg * 8);
        }
        cp_commit();
    };

    loadStage(0, 0);
    for (int step = 0; step < 16; step++) {
        int s = step & 1;
        if (step < 15) {
            loadStage(step + 1, s ^ 1);
            asm volatile("cp.async.wait_group 1;");
        } else {
            asm volatile("cp.async.wait_group 0;");
        }
        __syncthreads();

        uint32_t afr[2][4][4];
        #pragma unroll
        for (int v = 0; v < 2; v++)
            #pragma unroll
            for (int mi = 0; mi < 4; mi++) {
                const __nv_bfloat16* p = &sA[s][v][(wm * 64 + mi * 16 + (lane & 15)) * 16] + ((lane >> 4) & 1) * 8;
                ldsm_x4(afr[v][mi], p);
            }
        uint32_t bfr[2][4][2];
        #pragma unroll
        for (int v = 0; v < 2; v++)
            #pragma unroll
            for (int ni = 0; ni < 4; ni++) {
                const __nv_bfloat16* p = &sB[s][v][(lane & 15) * 136 + wn * 32 + ni * 8];
                ldsm_x2t(bfr[v][ni], p);
            }
        #pragma unroll
        for (int mi = 0; mi < 4; mi++)
            #pragma unroll
            for (int ni = 0; ni < 4; ni++) {
                mma16816(acc[mi][ni], afr[0][mi], bfr[0][ni]);
                mma16816(acc[mi][ni], afr[0][mi], bfr[1][ni]);
                mma16816(acc[mi][ni], afr[1][mi], bfr[0][ni]);
            }
        __syncthreads();
    }

    float* Yb = Y + (long)b * yStride;
    #pragma unroll
    for (int mi = 0; mi < 4; mi++) {
        int r0 = m0 + wm * 64 + mi * 16 + g;
        int r1 = r0 + 8;
        float bv0 = bias[r0], bv1 = bias[r1];
        #pragma unroll
        for (int ni = 0; ni < 4; ni++) {
            int col = n0 + wn * 32 + ni * 8 + 2 * t;
            Yb[(long)r0 * N_ + col]     = acc[mi][ni][0] + bv0;
            Yb[(long)r0 * N_ + col + 1] = acc[mi][ni][1] + bv0;
            Yb[(long)r1 * N_ + col]     = acc[mi][ni][2] + bv1;
            Yb[(long)r1 * N_ + col + 1] = acc[mi][ni][3] + bv1;
        }
    }
}

// ---------------- wide elementwise convert ----------------
__global__ __launch_bounds__(256) void convert_kernel() {
    int row = blockIdx.x;        // 0..767
    int b   = blockIdx.y;
    int n   = threadIdx.x * 4;
    const float QMUL = SCALE * LOG2E;

    float4 v = *reinterpret_cast<const float4*>(g_proj + ((long)b * PR_ + row) * N_ + n);
    uint2 outp;
    if (row < 256) {
        float4 s = *reinterpret_cast<const float4*>(g_sq + b * N_ + n);
        outp.x = packbf(v.x * s.x * QMUL, v.y * s.y * QMUL);
        outp.y = packbf(v.z * s.z * QMUL, v.w * s.w * QMUL);
        *reinterpret_cast<uint2*>(g_qB + ((long)b * C_ + row) * N_ + n) = outp;
    } else if (row < 512) {
        float4 s = *reinterpret_cast<const float4*>(g_sk + b * N_ + n);
        outp.x = packbf(v.x * s.x, v.y * s.y);
        outp.y = packbf(v.z * s.z, v.w * s.w);
        *reinterpret_cast<uint2*>(g_kB + ((long)b * C_ + row - 256) * N_ + n) = outp;
    } else {
        outp.x = packbf(v.x, v.y);
        outp.y = packbf(v.z, v.w);
        *reinterpret_cast<uint2*>(g_vB + ((long)b * C_ + row - 512) * N_ + n) = outp;
    }
}

// ---------------- flash attention: 128-key stages, two 64-key halves ----------------
#define QSTR 136
#define KSTR 136
__global__ __launch_bounds__(256) void attn_kernel() {
    int b = blockIdx.z, h = blockIdx.y;
    int n0 = blockIdx.x * 128;
    const __nv_bfloat16* qBp = g_qB + ((long)b * C_ + h * HD) * N_;
    const __nv_bfloat16* kBp = g_kB + ((long)b * C_ + h * HD) * N_;
    const __nv_bfloat16* vBp = g_vB + ((long)b * C_ + h * HD) * N_;

    __shared__ __align__(16) __nv_bfloat16 qsm[32 * QSTR];       // [d][q]
    __shared__ __align__(16) __nv_bfloat16 ksm[2][32 * KSTR];    // [stage][d][128 keys]
    __shared__ __align__(16) __nv_bfloat16 vsm[2][32 * KSTR];
    __shared__ float osm[32][130];

    int tid = threadIdx.x;
    int w = tid >> 5, lane = tid & 31;
    int g = lane >> 2, t = lane & 3;

    auto loadKV = [&](int m0, int s) {
        // 32 rows x 256B per array = 512 x 16B chunks; 2 per thread per array
        #pragma unroll
        for (int c = 0; c < 2; c++) {
            int idx = c * 256 + tid;
            int row = idx >> 4, seg = idx & 15;
            cp16(&ksm[s][row * KSTR + seg * 8], kBp + (long)row * N_ + m0 + seg * 8);
            cp16(&vsm[s][row * KSTR + seg * 8], vBp + (long)row * N_ + m0 + seg * 8);
        }
        cp_commit();
    };

    loadKV(0, 0);

    #pragma unroll
    for (int c = tid; c < 512; c += 256) {
        int row = c >> 4, seg = c & 15;
        reinterpret_cast<uint4*>(qsm + row * QSTR)[seg] =
            reinterpret_cast<const uint4*>(qBp + (long)row * N_ + n0)[seg];
    }
    __syncthreads();

    uint32_t aq[2][4];
    #pragma unroll
    for (int ku = 0; ku < 2; ku++) {
        int d = ku * 16 + ((lane >> 4) & 1) * 8 + (lane & 7);
        int col = w * 16 + ((lane >> 3) & 1) * 8;
        ldsm_x4t(aq[ku], qsm + d * QSTR + col);
    }

    float oacc[4][4];
    #pragma unroll
    for (int nd = 0; nd < 4; nd++)
        #pragma unroll
        for (int r = 0; r < 4; r++) oacc[nd][r] = 0.f;
    float l0 = 0.f, l1 = 0.f;

    for (int it = 0; it < 8; it++) {
        int s = it & 1;
        if (it < 7) {
            loadKV((it + 1) * 128, s ^ 1);
            asm volatile("cp.async.wait_group 1;");
        } else {
            asm volatile("cp.async.wait_group 0;");
        }
        __syncthreads();

        #pragma unroll
        for (int hh = 0; hh < 2; hh++) {
            int koff = hh * 64;
            float sS[8][4];
            #pragma unroll
            for (int ni = 0; ni < 8; ni++) {
                #pragma unroll
                for (int r = 0; r < 4; r++) sS[ni][r] = 0.f;
                #pragma unroll
                for (int ku = 0; ku < 2; ku++) {
                    uint32_t bk[2];
                    ldsm_x2t(bk, &ksm[s][(ku * 16 + (lane & 15)) * KSTR + koff + ni * 8]);
                    mma16816(sS[ni], aq[ku], bk);
                }
            }

            #pragma unroll
            for (int ni = 0; ni < 8; ni++) {
                sS[ni][0] = ex2(sS[ni][0]); l0 += sS[ni][0];
                sS[ni][1] = ex2(sS[ni][1]); l0 += sS[ni][1];
                sS[ni][2] = ex2(sS[ni][2]); l1 += sS[ni][2];
                sS[ni][3] = ex2(sS[ni][3]); l1 += sS[ni][3];
            }

            #pragma unroll
            for (int u = 0; u < 4; u++) {
                uint32_t ap[4];
                ap[0] = packbf(sS[2*u][0],   sS[2*u][1]);
                ap[1] = packbf(sS[2*u][2],   sS[2*u][3]);
                ap[2] = packbf(sS[2*u+1][0], sS[2*u+1][1]);
                ap[3] = packbf(sS[2*u+1][2], sS[2*u+1][3]);
                #pragma unroll
                for (int nd = 0; nd < 4; nd++) {
                    uint32_t bv[2];
                    ldsm_x2(bv, &vsm[s][(nd * 8 + (lane & 7)) * KSTR + koff + u * 16 + ((lane >> 3) & 1) * 8]);
                    mma16816(oacc[nd], ap, bv);
                }
            }
        }
        __syncthreads();
    }

    #pragma unroll
    for (int off = 1; off < 4; off <<= 1) {
        l0 += __shfl_xor_sync(0xffffffffu, l0, off);
        l1 += __shfl_xor_sync(0xffffffffu, l1, off);
    }
    float inv0 = 1.f / l0, inv1 = 1.f / l1;

    #pragma unroll
    for (int nd = 0; nd < 4; nd++) {
        osm[nd * 8 + 2 * t][w * 16 + g]         = oacc[nd][0] * inv0;
        osm[nd * 8 + 2 * t + 1][w * 16 + g]     = oacc[nd][1] * inv0;
        osm[nd * 8 + 2 * t][w * 16 + g + 8]     = oacc[nd][2] * inv1;
        osm[nd * 8 + 2 * t + 1][w * 16 + g + 8] = oacc[nd][3] * inv1;
    }
    __syncthreads();

    const float* vfull = g_proj + ((long)b * PR_ + 512 + h * HD) * N_ + n0;
    int n = tid & 127;
    float sqv = g_sq[b * N_ + n0 + n];
    #pragma unroll
    for (int d = tid >> 7; d < HD; d += 2) {
        float gated = sqv * osm[d][n] + (1.f - sqv) * vfull[(long)d * N_ + n];
        __nv_bfloat16 hi, lo; split_bf(gated, hi, lo);
        long gidx = ((long)b * C_ + h * HD + d) * N_ + n0 + n;
        g_ghi[gidx] = hi; g_glo[gidx] = lo;
    }
}

// ---------------- launch ----------------
extern "C" void kernel_launch(void* const* d_in, const int* in_sizes, int n_in,
                              void* d_out, int out_size) {
    const float* x   = (const float*)d_in[0];
    const float* gq  = (const float*)d_in[1];
    const float* gk  = (const float*)d_in[2];
    const float* Wsq = (const float*)d_in[3];
    const float* bsq = (const float*)d_in[4];
    const float* Wsk = (const float*)d_in[5];
    const float* bsk = (const float*)d_in[6];
    const float* Wq  = (const float*)d_in[7];
    const float* bq  = (const float*)d_in[8];
    const float* Wk  = (const float*)d_in[9];
    const float* bk  = (const float*)d_in[10];
    const float* Wv  = (const float*)d_in[11];
    const float* bv  = (const float*)d_in[12];
    const float* Wp  = (const float*)d_in[13];
    const float* bp  = (const float*)d_in[14];
    float* out = (float*)d_out;

    void *whi, *wlo, *ball, *wphi, *wplo, *xhi, *xlo, *proj, *ghi, *glo;
    cudaGetSymbolAddress(&whi,  g_whi);
    cudaGetSymbolAddress(&wlo,  g_wlo);
    cudaGetSymbolAddress(&ball, g_ball);
    cudaGetSymbolAddress(&wphi, g_wphi);
    cudaGetSymbolAddress(&wplo, g_wplo);
    cudaGetSymbolAddress(&xhi,  g_xhi);
    cudaGetSymbolAddress(&xlo,  g_xlo);
    cudaGetSymbolAddress(&proj, g_proj);
    cudaGetSymbolAddress(&ghi,  g_ghi);
    cudaGetSymbolAddress(&glo,  g_glo);

    assemble_split_kernel<<<PR_ + C_, 256>>>(Wq, bq, Wk, bk, Wv, bv, Wp);
    xsplit_kernel<<<(B_ * C_ * N_) / 1024, 256>>>(x);

    {   // gate projection + softmax (fp32, straight from x)
        dim3 g(8, B_);
        gateproj_kernel<<<g, 128>>>(x, gq, gk, Wsq, bsq, Wsk, bsk);
    }

    {   // proj = W_qkv @ x  (bf16x3), 768 rows
        dim3 g(N_ / 128, PR_ / 128, B_);
        gemm3x_kernel<<<g, 256>>>((const __nv_bfloat16*)whi, (const __nv_bfloat16*)wlo,
                                  (const float*)ball,
                                  (const __nv_bfloat16*)xhi, (const __nv_bfloat16*)xlo,
                                  (float*)proj, (long)C_ * N_, (long)PR_ * N_);
    }

    {   // wide elementwise convert
        dim3 g(PR_, B_);
        convert_kernel<<<g, 256>>>();
    }

    {   // attention + blend
        dim3 g(N_ / 128, NH, B_);
        attn_kernel<<<g, 256>>>();
    }

    {   // out = Wp @ gated  (bf16x3)
        dim3 g(N_ / 128, C_ / 128, B_);
        gemm3x_kernel<<<g, 256>>>((const __nv_bfloat16*)wphi, (const __nv_bfloat16*)wplo,
                                  bp,
                                  (const __nv_bfloat16*)ghi, (const __nv_bfloat16*)glo,
                                  out, (long)C_ * N_, (long)C_ * N_);
    }
}

// round 8
// speedup vs baseline: 1.2055x; 1.2055x over previous
#include <cuda_runtime.h>
#include <cuda_bf16.h>
#include <cstdint>

#define B_    8
#define C_    256
#define N_    1024
#define NH    8
#define HD    32
#define R_    4
#define MTOT  776
#define SCALE 0.17677669529663689f
#define LOG2E 1.4426950408889634f

// ---------------- scratch ----------------
__device__ float g_proj[B_ * MTOT * N_];
__device__ float g_sq[B_ * N_];
__device__ float g_sk[B_ * N_];
__device__ float g_ball[MTOT];
__device__ __nv_bfloat16 g_whi[MTOT * C_], g_wlo[MTOT * C_];
__device__ __nv_bfloat16 g_wphi[C_ * C_], g_wplo[C_ * C_];
__device__ __nv_bfloat16 g_xhi[B_ * C_ * N_], g_xlo[B_ * C_ * N_];
__device__ __nv_bfloat16 g_qB[B_ * C_ * N_];   // gated*SCALE*LOG2E
__device__ __nv_bfloat16 g_kB[B_ * C_ * N_];   // gated
__device__ __nv_bfloat16 g_vB[B_ * C_ * N_];
__device__ __nv_bfloat16 g_ghi[B_ * C_ * N_], g_glo[B_ * C_ * N_];

// ---------------- ptx helpers ----------------
__device__ __forceinline__ void cp16(void* d, const void* s) {
    uint32_t ds = (uint32_t)__cvta_generic_to_shared(d);
    asm volatile("cp.async.cg.shared.global [%0], [%1], 16;" :: "r"(ds), "l"(s));
}
__device__ __forceinline__ void cp_commit() { asm volatile("cp.async.commit_group;"); }

__device__ __forceinline__ void ldsm_x4(uint32_t (&r)[4], const void* p) {
    uint32_t a = (uint32_t)__cvta_generic_to_shared(p);
    asm volatile("ldmatrix.sync.aligned.m8n8.x4.shared.b16 {%0,%1,%2,%3},[%4];"
                 : "=r"(r[0]), "=r"(r[1]), "=r"(r[2]), "=r"(r[3]) : "r"(a));
}
__device__ __forceinline__ void ldsm_x4t(uint32_t (&r)[4], const void* p) {
    uint32_t a = (uint32_t)__cvta_generic_to_shared(p);
    asm volatile("ldmatrix.sync.aligned.m8n8.x4.trans.shared.b16 {%0,%1,%2,%3},[%4];"
                 : "=r"(r[0]), "=r"(r[1]), "=r"(r[2]), "=r"(r[3]) : "r"(a));
}
__device__ __forceinline__ void ldsm_x2(uint32_t (&r)[2], const void* p) {
    uint32_t a = (uint32_t)__cvta_generic_to_shared(p);
    asm volatile("ldmatrix.sync.aligned.m8n8.x2.shared.b16 {%0,%1},[%2];"
                 : "=r"(r[0]), "=r"(r[1]) : "r"(a));
}
__device__ __forceinline__ void ldsm_x2t(uint32_t (&r)[2], const void* p) {
    uint32_t a = (uint32_t)__cvta_generic_to_shared(p);
    asm volatile("ldmatrix.sync.aligned.m8n8.x2.trans.shared.b16 {%0,%1},[%2];"
                 : "=r"(r[0]), "=r"(r[1]) : "r"(a));
}
__device__ __forceinline__ void mma16816(float (&d)[4], const uint32_t (&a)[4], const uint32_t (&b)[2]) {
    asm volatile(
        "mma.sync.aligned.m16n8k16.row.col.f32.bf16.bf16.f32 "
        "{%0,%1,%2,%3},{%4,%5,%6,%7},{%8,%9},{%0,%1,%2,%3};"
        : "+f"(d[0]), "+f"(d[1]), "+f"(d[2]), "+f"(d[3])
        : "r"(a[0]), "r"(a[1]), "r"(a[2]), "r"(a[3]), "r"(b[0]), "r"(b[1]));
}
__device__ __forceinline__ uint32_t packbf(float lo, float hi) {
    __nv_bfloat162 t = __floats2bfloat162_rn(lo, hi);
    return *reinterpret_cast<uint32_t*>(&t);
}
__device__ __forceinline__ float ex2(float x) {
    float y; asm("ex2.approx.ftz.f32 %0,%1;" : "=f"(y) : "f"(x)); return y;
}
__device__ __forceinline__ void split_bf(float x, __nv_bfloat16& hi, __nv_bfloat16& lo) {
    hi = __float2bfloat16_rn(x);
    lo = __float2bfloat16_rn(x - __bfloat162float(hi));
}

// ---------------- assemble + split weights ----------------
__global__ void assemble_split_kernel(
    const float* __restrict__ Wq, const float* __restrict__ bq,
    const float* __restrict__ Wk, const float* __restrict__ bk,
    const float* __restrict__ Wv, const float* __restrict__ bv,
    const float* __restrict__ Wsq, const float* __restrict__ bsq,
    const float* __restrict__ Wsk, const float* __restrict__ bsk,
    const float* __restrict__ Wp)
{
    int o = blockIdx.x;
    int k = threadIdx.x;
    if (o < MTOT) {
        const float* src; const float* bs; int r;
        if (o < 256)      { src = Wq  + o * 256;       bs = bq;  r = o; }
        else if (o < 512) { src = Wk  + (o-256) * 256; bs = bk;  r = o - 256; }
        else if (o < 768) { src = Wv  + (o-512) * 256; bs = bv;  r = o - 512; }
        else if (o < 772) { src = Wsq + (o-768) * 256; bs = bsq; r = o - 768; }
        else              { src = Wsk + (o-772) * 256; bs = bsk; r = o - 772; }
        __nv_bfloat16 hi, lo; split_bf(src[k], hi, lo);
        g_whi[o * 256 + k] = hi; g_wlo[o * 256 + k] = lo;
        if (k == 0) g_ball[o] = bs[r];
    } else {
        int r = o - MTOT;
        __nv_bfloat16 hi, lo; split_bf(Wp[r * 256 + k], hi, lo);
        g_wphi[r * 256 + k] = hi; g_wplo[r * 256 + k] = lo;
    }
}

// ---------------- split x into bf16 hi/lo (float4) ----------------
__global__ void xsplit_kernel(const float* __restrict__ x) {
    int i = (blockIdx.x * 256 + threadIdx.x) * 4;
    float4 v = *reinterpret_cast<const float4*>(x + i);
    __nv_bfloat16 h0,l0,h1,l1,h2,l2,h3,l3;
    split_bf(v.x,h0,l0); split_bf(v.y,h1,l1); split_bf(v.z,h2,l2); split_bf(v.w,h3,l3);
    uint2 ph, pl;
    ph.x = ((uint32_t)*(uint16_t*)&h1 << 16) | *(uint16_t*)&h0;
    ph.y = ((uint32_t)*(uint16_t*)&h3 << 16) | *(uint16_t*)&h2;
    pl.x = ((uint32_t)*(uint16_t*)&l1 << 16) | *(uint16_t*)&l0;
    pl.y = ((uint32_t)*(uint16_t*)&l3 << 16) | *(uint16_t*)&l2;
    *reinterpret_cast<uint2*>(g_xhi + i) = ph;
    *reinterpret_cast<uint2*>(g_xlo + i) = pl;
}

// ---------------- bf16x3 GEMM, 3-stage cp.async pipeline ----------------
__global__ __launch_bounds__(256) void gemm3x_kernel(
    const __nv_bfloat16* __restrict__ Whi, const __nv_bfloat16* __restrict__ Wlo,
    const float* __restrict__ bias,
    const __nv_bfloat16* __restrict__ Xhi, const __nv_bfloat16* __restrict__ Xlo,
    float* __restrict__ Y, int M, long xStride, long yStride)
{
    int b  = blockIdx.z;
    int m0 = blockIdx.y * 128;
    int n0 = blockIdx.x * 128;
    const __nv_bfloat16* XhiB = Xhi + (long)b * xStride;
    const __nv_bfloat16* XloB = Xlo + (long)b * xStride;

    __shared__ __align__(16) __nv_bfloat16 sA[3][2][128 * 16];
    __shared__ __align__(16) __nv_bfloat16 sB[3][2][16 * 136];

    int tid  = threadIdx.x;
    int warp = tid >> 5, lane = tid & 31;
    int wm = warp >> 2, wn = warp & 3;
    int g = lane >> 2, t = lane & 3;

    float acc[4][4][4];
    #pragma unroll
    for (int mi = 0; mi < 4; mi++)
        #pragma unroll
        for (int ni = 0; ni < 4; ni++)
            #pragma unroll
            for (int r = 0; r < 4; r++) acc[mi][ni][r] = 0.f;

    auto loadStage = [&](int step, int s) {
        int k0 = step * 16;
        {
            int row = tid >> 1, half = tid & 1;
            int gm = m0 + row;
            __nv_bfloat16* dhi = &sA[s][0][row * 16 + half * 8];
            __nv_bfloat16* dlo = &sA[s][1][row * 16 + half * 8];
            if (gm < M) {
                cp16(dhi, Whi + gm * 256 + k0 + half * 8);
                cp16(dlo, Wlo + gm * 256 + k0 + half * 8);
            } else {
                *reinterpret_cast<uint4*>(dhi) = make_uint4(0,0,0,0);
                *reinterpret_cast<uint4*>(dlo) = make_uint4(0,0,0,0);
            }
        }
        {
            int row = tid >> 4, seg = tid & 15;
            cp16(&sB[s][0][row * 136 + seg * 8], XhiB + (long)(k0 + row) * N_ + n0 + seg * 8);
            cp16(&sB[s][1][row * 136 + seg * 8], XloB + (long)(k0 + row) * N_ + n0 + seg * 8);
        }
        cp_commit();
    };

    loadStage(0, 0);
    loadStage(1, 1);
    for (int step = 0; step < 16; step++) {
        int s = step % 3;
        if (step < 14) {
            loadStage(step + 2, (step + 2) % 3);
            asm volatile("cp.async.wait_group 2;");
        } else if (step == 14) {
            asm volatile("cp.async.wait_group 1;");
        } else {
            asm volatile("cp.async.wait_group 0;");
        }
        __syncthreads();

        uint32_t afr[2][4][4];
        #pragma unroll
        for (int v = 0; v < 2; v++)
            #pragma unroll
            for (int mi = 0; mi < 4; mi++) {
                const __nv_bfloat16* p = &sA[s][v][(wm * 64 + mi * 16 + (lane & 15)) * 16] + ((lane >> 4) & 1) * 8;
                ldsm_x4(afr[v][mi], p);
            }
        uint32_t bfr[2][4][2];
        #pragma unroll
        for (int v = 0; v < 2; v++)
            #pragma unroll
            for (int ni = 0; ni < 4; ni++) {
                const __nv_bfloat16* p = &sB[s][v][(lane & 15) * 136 + wn * 32 + ni * 8];
                ldsm_x2t(bfr[v][ni], p);
            }
        #pragma unroll
        for (int mi = 0; mi < 4; mi++)
            #pragma unroll
            for (int ni = 0; ni < 4; ni++) {
                mma16816(acc[mi][ni], afr[0][mi], bfr[0][ni]);
                mma16816(acc[mi][ni], afr[0][mi], bfr[1][ni]);
                mma16816(acc[mi][ni], afr[1][mi], bfr[0][ni]);
            }
        __syncthreads();
    }

    float* Yb = Y + (long)b * yStride;
    #pragma unroll
    for (int mi = 0; mi < 4; mi++) {
        int r0 = m0 + wm * 64 + mi * 16 + g;
        int r1 = r0 + 8;
        #pragma unroll
        for (int ni = 0; ni < 4; ni++) {
            int col = n0 + wn * 32 + ni * 8 + 2 * t;
            if (r0 < M) {
                float bv = bias[r0];
                Yb[(long)r0 * N_ + col]     = acc[mi][ni][0] + bv;
                Yb[(long)r0 * N_ + col + 1] = acc[mi][ni][1] + bv;
            }
            if (r1 < M) {
                float bv = bias[r1];
                Yb[(long)r1 * N_ + col]     = acc[mi][ni][2] + bv;
                Yb[(long)r1 * N_ + col + 1] = acc[mi][ni][3] + bv;
            }
        }
    }
}

// ---------------- gates: 4-way softmax per pixel ----------------
__global__ void gates_kernel(const float* __restrict__ gq, const float* __restrict__ gk) {
    int idx = blockIdx.x * blockDim.x + threadIdx.x;
    if (idx >= B_ * N_) return;
    int b = idx >> 10, n = idx & 1023;
    const float* pr = g_proj + (long)b * MTOT * N_;
    float lq[R_], lk[R_];
    #pragma unroll
    for (int r = 0; r < R_; r++) {
        lq[r] = pr[(768 + r) * N_ + n] + gq[(b * R_ + r) * N_ + n];
        lk[r] = pr[(772 + r) * N_ + n] + gk[(b * R_ + r) * N_ + n];
    }
    float mq = fmaxf(fmaxf(lq[0], lq[1]), fmaxf(lq[2], lq[3]));
    float s = 0.f;
    #pragma unroll
    for (int r = 0; r < R_; r++) s += __expf(lq[r] - mq);
    g_sq[idx] = __expf(lq[0] - mq) / s;
    float mk = fmaxf(fmaxf(lk[0], lk[1]), fmaxf(lk[2], lk[3]));
    s = 0.f;
    #pragma unroll
    for (int r = 0; r < R_; r++) s += __expf(lk[r] - mk);
    g_sk[idx] = __expf(lk[0] - mk) / s;
}

// ---------------- wide elementwise convert ----------------
__global__ __launch_bounds__(256) void convert_kernel() {
    int row = blockIdx.x;        // 0..767
    int b   = blockIdx.y;
    int n   = threadIdx.x * 4;
    const float QMUL = SCALE * LOG2E;

    float4 v = *reinterpret_cast<const float4*>(g_proj + ((long)b * MTOT + row) * N_ + n);
    uint2 outp;
    if (row < 256) {
        float4 s = *reinterpret_cast<const float4*>(g_sq + b * N_ + n);
        outp.x = packbf(v.x * s.x * QMUL, v.y * s.y * QMUL);
        outp.y = packbf(v.z * s.z * QMUL, v.w * s.w * QMUL);
        *reinterpret_cast<uint2*>(g_qB + ((long)b * C_ + row) * N_ + n) = outp;
    } else if (row < 512) {
        float4 s = *reinterpret_cast<const float4*>(g_sk + b * N_ + n);
        outp.x = packbf(v.x * s.x, v.y * s.y);
        outp.y = packbf(v.z * s.z, v.w * s.w);
        *reinterpret_cast<uint2*>(g_kB + ((long)b * C_ + row - 256) * N_ + n) = outp;
    } else {
        outp.x = packbf(v.x, v.y);
        outp.y = packbf(v.z, v.w);
        *reinterpret_cast<uint2*>(g_vB + ((long)b * C_ + row - 512) * N_ + n) = outp;
    }
}

// ---------------- flash attention, no-max softmax, 128 queries/block, 64-key stages ----------------
#define QSTR 136
#define KSTR 72
__global__ __launch_bounds__(256) void attn_kernel() {
    int b = blockIdx.z, h = blockIdx.y;
    int n0 = blockIdx.x * 128;
    const __nv_bfloat16* qBp = g_qB + ((long)b * C_ + h * HD) * N_;
    const __nv_bfloat16* kBp = g_kB + ((long)b * C_ + h * HD) * N_;
    const __nv_bfloat16* vBp = g_vB + ((long)b * C_ + h * HD) * N_;

    __shared__ __align__(16) __nv_bfloat16 qsm[32 * QSTR];       // [d][q]
    __shared__ __align__(16) __nv_bfloat16 ksm[2][32 * KSTR];    // [stage][d][key]
    __shared__ __align__(16) __nv_bfloat16 vsm[2][32 * KSTR];
    __shared__ float osm[32][130];

    int tid = threadIdx.x;
    int w = tid >> 5, lane = tid & 31;
    int g = lane >> 2, t = lane & 3;

    auto loadKV = [&](int m0, int s) {
        int row = tid >> 3, seg = tid & 7;
        cp16(&ksm[s][row * KSTR + seg * 8], kBp + (long)row * N_ + m0 + seg * 8);
        cp16(&vsm[s][row * KSTR + seg * 8], vBp + (long)row * N_ + m0 + seg * 8);
        cp_commit();
    };

    loadKV(0, 0);

    #pragma unroll
    for (int c = tid; c < 512; c += 256) {
        int row = c >> 4, seg = c & 15;
        reinterpret_cast<uint4*>(qsm + row * QSTR)[seg] =
            reinterpret_cast<const uint4*>(qBp + (long)row * N_ + n0)[seg];
    }
    __syncthreads();

    uint32_t aq[2][4];
    #pragma unroll
    for (int ku = 0; ku < 2; ku++) {
        int d = ku * 16 + ((lane >> 4) & 1) * 8 + (lane & 7);
        int col = w * 16 + ((lane >> 3) & 1) * 8;
        ldsm_x4t(aq[ku], qsm + d * QSTR + col);
    }

    float oacc[4][4];
    #pragma unroll
    for (int nd = 0; nd < 4; nd++)
        #pragma unroll
        for (int r = 0; r < 4; r++) oacc[nd][r] = 0.f;
    float l0 = 0.f, l1 = 0.f;

    for (int it = 0; it < 16; it++) {
        int s = it & 1;
        if (it < 15) {
            loadKV((it + 1) * 64, s ^ 1);
            asm volatile("cp.async.wait_group 1;");
        } else {
            asm volatile("cp.async.wait_group 0;");
        }
        __syncthreads();

        float sS[8][4];
        #pragma unroll
        for (int ni = 0; ni < 8; ni++) {
            #pragma unroll
            for (int r = 0; r < 4; r++) sS[ni][r] = 0.f;
            #pragma unroll
            for (int ku = 0; ku < 2; ku++) {
                uint32_t bk[2];
                ldsm_x2t(bk, &ksm[s][(ku * 16 + (lane & 15)) * KSTR + ni * 8]);
                mma16816(sS[ni], aq[ku], bk);
            }
        }

        #pragma unroll
        for (int ni = 0; ni < 8; ni++) {
            sS[ni][0] = ex2(sS[ni][0]); l0 += sS[ni][0];
            sS[ni][1] = ex2(sS[ni][1]); l0 += sS[ni][1];
            sS[ni][2] = ex2(sS[ni][2]); l1 += sS[ni][2];
            sS[ni][3] = ex2(sS[ni][3]); l1 += sS[ni][3];
        }

        #pragma unroll
        for (int u = 0; u < 4; u++) {
            uint32_t ap[4];
            ap[0] = packbf(sS[2*u][0],   sS[2*u][1]);
            ap[1] = packbf(sS[2*u][2],   sS[2*u][3]);
            ap[2] = packbf(sS[2*u+1][0], sS[2*u+1][1]);
            ap[3] = packbf(sS[2*u+1][2], sS[2*u+1][3]);
            #pragma unroll
            for (int nd = 0; nd < 4; nd++) {
                uint32_t bv[2];
                ldsm_x2(bv, &vsm[s][(nd * 8 + (lane & 7)) * KSTR + u * 16 + ((lane >> 3) & 1) * 8]);
                mma16816(oacc[nd], ap, bv);
            }
        }
        __syncthreads();
    }

    #pragma unroll
    for (int off = 1; off < 4; off <<= 1) {
        l0 += __shfl_xor_sync(0xffffffffu, l0, off);
        l1 += __shfl_xor_sync(0xffffffffu, l1, off);
    }
    float inv0 = 1.f / l0, inv1 = 1.f / l1;

    #pragma unroll
    for (int nd = 0; nd < 4; nd++) {
        osm[nd * 8 + 2 * t][w * 16 + g]         = oacc[nd][0] * inv0;
        osm[nd * 8 + 2 * t + 1][w * 16 + g]     = oacc[nd][1] * inv0;
        osm[nd * 8 + 2 * t][w * 16 + g + 8]     = oacc[nd][2] * inv1;
        osm[nd * 8 + 2 * t + 1][w * 16 + g + 8] = oacc[nd][3] * inv1;
    }
    __syncthreads();

    const float* vfull = g_proj + ((long)b * MTOT + 512 + h * HD) * N_ + n0;
    int n = tid & 127;
    float sqv = g_sq[b * N_ + n0 + n];
    #pragma unroll
    for (int d = tid >> 7; d < HD; d += 2) {
        float gated = sqv * osm[d][n] + (1.f - sqv) * vfull[(long)d * N_ + n];
        __nv_bfloat16 hi, lo; split_bf(gated, hi, lo);
        long gidx = ((long)b * C_ + h * HD + d) * N_ + n0 + n;
        g_ghi[gidx] = hi; g_glo[gidx] = lo;
    }
}

// ---------------- launch ----------------
extern "C" void kernel_launch(void* const* d_in, const int* in_sizes, int n_in,
                              void* d_out, int out_size) {
    const float* x   = (const float*)d_in[0];
    const float* gq  = (const float*)d_in[1];
    const float* gk  = (const float*)d_in[2];
    const float* Wsq = (const float*)d_in[3];
    const float* bsq = (const float*)d_in[4];
    const float* Wsk = (const float*)d_in[5];
    const float* bsk = (const float*)d_in[6];
    const float* Wq  = (const float*)d_in[7];
    const float* bq  = (const float*)d_in[8];
    const float* Wk  = (const float*)d_in[9];
    const float* bk  = (const float*)d_in[10];
    const float* Wv  = (const float*)d_in[11];
    const float* bv  = (const float*)d_in[12];
    const float* Wp  = (const float*)d_in[13];
    const float* bp  = (const float*)d_in[14];
    float* out = (float*)d_out;

    void *whi, *wlo, *ball, *wphi, *wplo, *xhi, *xlo, *proj, *ghi, *glo;
    cudaGetSymbolAddress(&whi,  g_whi);
    cudaGetSymbolAddress(&wlo,  g_wlo);
    cudaGetSymbolAddress(&ball, g_ball);
    cudaGetSymbolAddress(&wphi, g_wphi);
    cudaGetSymbolAddress(&wplo, g_wplo);
    cudaGetSymbolAddress(&xhi,  g_xhi);
    cudaGetSymbolAddress(&xlo,  g_xlo);
    cudaGetSymbolAddress(&proj, g_proj);
    cudaGetSymbolAddress(&ghi,  g_ghi);
    cudaGetSymbolAddress(&glo,  g_glo);

    assemble_split_kernel<<<MTOT + C_, 256>>>(Wq, bq, Wk, bk, Wv, bv, Wsq, bsq, Wsk, bsk, Wp);
    xsplit_kernel<<<(B_ * C_ * N_) / 1024, 256>>>(x);

    {   // proj = Wall @ x  (bf16x3)
        dim3 g(N_ / 128, (MTOT + 127) / 128, B_);
        gemm3x_kernel<<<g, 256>>>((const __nv_bfloat16*)whi, (const __nv_bfloat16*)wlo,
                                  (const float*)ball,
                                  (const __nv_bfloat16*)xhi, (const __nv_bfloat16*)xlo,
                                  (float*)proj, MTOT, (long)C_ * N_, (long)MTOT * N_);
    }

    gates_kernel<<<(B_ * N_ + 255) / 256, 256>>>(gq, gk);

    {   // wide elementwise convert
        dim3 g(768, B_);
        convert_kernel<<<g, 256>>>();
    }

    {   // attention + blend
        dim3 g(N_ / 128, NH, B_);
        attn_kernel<<<g, 256>>>();
    }

    {   // out = Wp @ gated  (bf16x3)
        dim3 g(N_ / 128, C_ / 128, B_);
        gemm3x_kernel<<<g, 256>>>((const __nv_bfloat16*)wphi, (const __nv_bfloat16*)wplo,
                                  bp,
                                  (const __nv_bfloat16*)ghi, (const __nv_bfloat16*)glo,
                                  out, C_, (long)C_ * N_, (long)C_ * N_);
    }
}

// round 9
// speedup vs baseline: 1.2670x; 1.0510x over previous
#include <cuda_runtime.h>
#include <cuda_bf16.h>
#include <cstdint>

#define B_    8
#define C_    256
#define N_    1024
#define NH    8
#define HD    32
#define R_    4
#define MTOT  776
#define SCALE 0.17677669529663689f
#define LOG2E 1.4426950408889634f

// ---------------- scratch ----------------
__device__ float g_proj[B_ * MTOT * N_];
__device__ float g_sq[B_ * N_];
__device__ float g_sk[B_ * N_];
__device__ float g_ball[MTOT];
__device__ __nv_bfloat16 g_whi[MTOT * C_], g_wlo[MTOT * C_];
__device__ __nv_bfloat16 g_wphi[C_ * C_], g_wplo[C_ * C_];
__device__ __nv_bfloat16 g_xhi[B_ * C_ * N_], g_xlo[B_ * C_ * N_];
__device__ __nv_bfloat16 g_qB[B_ * C_ * N_];   // gated*SCALE*LOG2E
__device__ __nv_bfloat16 g_kB[B_ * C_ * N_];   // gated
__device__ __nv_bfloat16 g_vB[B_ * C_ * N_];
__device__ __nv_bfloat16 g_ghi[B_ * C_ * N_], g_glo[B_ * C_ * N_];

// ---------------- ptx helpers ----------------
__device__ __forceinline__ void cp16(void* d, const void* s) {
    uint32_t ds = (uint32_t)__cvta_generic_to_shared(d);
    asm volatile("cp.async.cg.shared.global [%0], [%1], 16;" :: "r"(ds), "l"(s));
}
__device__ __forceinline__ void cp_commit() { asm volatile("cp.async.commit_group;"); }

__device__ __forceinline__ void ldsm_x4(uint32_t (&r)[4], const void* p) {
    uint32_t a = (uint32_t)__cvta_generic_to_shared(p);
    asm volatile("ldmatrix.sync.aligned.m8n8.x4.shared.b16 {%0,%1,%2,%3},[%4];"
                 : "=r"(r[0]), "=r"(r[1]), "=r"(r[2]), "=r"(r[3]) : "r"(a));
}
__device__ __forceinline__ void ldsm_x4t(uint32_t (&r)[4], const void* p) {
    uint32_t a = (uint32_t)__cvta_generic_to_shared(p);
    asm volatile("ldmatrix.sync.aligned.m8n8.x4.trans.shared.b16 {%0,%1,%2,%3},[%4];"
                 : "=r"(r[0]), "=r"(r[1]), "=r"(r[2]), "=r"(r[3]) : "r"(a));
}
__device__ __forceinline__ void ldsm_x2(uint32_t (&r)[2], const void* p) {
    uint32_t a = (uint32_t)__cvta_generic_to_shared(p);
    asm volatile("ldmatrix.sync.aligned.m8n8.x2.shared.b16 {%0,%1},[%2];"
                 : "=r"(r[0]), "=r"(r[1]) : "r"(a));
}
__device__ __forceinline__ void ldsm_x2t(uint32_t (&r)[2], const void* p) {
    uint32_t a = (uint32_t)__cvta_generic_to_shared(p);
    asm volatile("ldmatrix.sync.aligned.m8n8.x2.trans.shared.b16 {%0,%1},[%2];"
                 : "=r"(r[0]), "=r"(r[1]) : "r"(a));
}
__device__ __forceinline__ void mma16816(float (&d)[4], const uint32_t (&a)[4], const uint32_t (&b)[2]) {
    asm volatile(
        "mma.sync.aligned.m16n8k16.row.col.f32.bf16.bf16.f32 "
        "{%0,%1,%2,%3},{%4,%5,%6,%7},{%8,%9},{%0,%1,%2,%3};"
        : "+f"(d[0]), "+f"(d[1]), "+f"(d[2]), "+f"(d[3])
        : "r"(a[0]), "r"(a[1]), "r"(a[2]), "r"(a[3]), "r"(b[0]), "r"(b[1]));
}
__device__ __forceinline__ uint32_t packbf(float lo, float hi) {
    __nv_bfloat162 t = __floats2bfloat162_rn(lo, hi);
    return *reinterpret_cast<uint32_t*>(&t);
}
// pack two fp32 -> bf16x2 with one cvt (lo = second arg)
__device__ __forceinline__ uint32_t cvt2bf(float hi, float lo) {
    uint32_t y; asm("cvt.rn.bf16x2.f32 %0, %1, %2;" : "=r"(y) : "f"(hi), "f"(lo)); return y;
}
// 2^x on packed bf16x2
__device__ __forceinline__ uint32_t ex2_bf16x2(uint32_t x) {
    uint32_t y; asm("ex2.approx.ftz.bf16x2 %0, %1;" : "=r"(y) : "r"(x)); return y;
}
__device__ __forceinline__ void split_bf(float x, __nv_bfloat16& hi, __nv_bfloat16& lo) {
    hi = __float2bfloat16_rn(x);
    lo = __float2bfloat16_rn(x - __bfloat162float(hi));
}

// ---------------- assemble + split weights ----------------
__global__ void assemble_split_kernel(
    const float* __restrict__ Wq, const float* __restrict__ bq,
    const float* __restrict__ Wk, const float* __restrict__ bk,
    const float* __restrict__ Wv, const float* __restrict__ bv,
    const float* __restrict__ Wsq, const float* __restrict__ bsq,
    const float* __restrict__ Wsk, const float* __restrict__ bsk,
    const float* __restrict__ Wp)
{
    int o = blockIdx.x;
    int k = threadIdx.x;
    if (o < MTOT) {
        const float* src; const float* bs; int r;
        if (o < 256)      { src = Wq  + o * 256;       bs = bq;  r = o; }
        else if (o < 512) { src = Wk  + (o-256) * 256; bs = bk;  r = o - 256; }
        else if (o < 768) { src = Wv  + (o-512) * 256; bs = bv;  r = o - 512; }
        else if (o < 772) { src = Wsq + (o-768) * 256; bs = bsq; r = o - 768; }
        else              { src = Wsk + (o-772) * 256; bs = bsk; r = o - 772; }
        __nv_bfloat16 hi, lo; split_bf(src[k], hi, lo);
        g_whi[o * 256 + k] = hi; g_wlo[o * 256 + k] = lo;
        if (k == 0) g_ball[o] = bs[r];
    } else {
        int r = o - MTOT;
        __nv_bfloat16 hi, lo; split_bf(Wp[r * 256 + k], hi, lo);
        g_wphi[r * 256 + k] = hi; g_wplo[r * 256 + k] = lo;
    }
}

// ---------------- split x into bf16 hi/lo (float4) ----------------
__global__ void xsplit_kernel(const float* __restrict__ x) {
    int i = (blockIdx.x * 256 + threadIdx.x) * 4;
    float4 v = *reinterpret_cast<const float4*>(x + i);
    __nv_bfloat16 h0,l0,h1,l1,h2,l2,h3,l3;
    split_bf(v.x,h0,l0); split_bf(v.y,h1,l1); split_bf(v.z,h2,l2); split_bf(v.w,h3,l3);
    uint2 ph, pl;
    ph.x = ((uint32_t)*(uint16_t*)&h1 << 16) | *(uint16_t*)&h0;
    ph.y = ((uint32_t)*(uint16_t*)&h3 << 16) | *(uint16_t*)&h2;
    pl.x = ((uint32_t)*(uint16_t*)&l1 << 16) | *(uint16_t*)&l0;
    pl.y = ((uint32_t)*(uint16_t*)&l3 << 16) | *(uint16_t*)&l2;
    *reinterpret_cast<uint2*>(g_xhi + i) = ph;
    *reinterpret_cast<uint2*>(g_xlo + i) = pl;
}

// ---------------- bf16x3 GEMM, 2-stage, padded A (conflict-free ldsm), fused gates ----------------
#define ASTR 24   // A smem row stride in elements (48B: 8-row ldsm phases cover all banks)
__global__ __launch_bounds__(256) void gemm3x_kernel(
    const __nv_bfloat16* __restrict__ Whi, const __nv_bfloat16* __restrict__ Wlo,
    const float* __restrict__ bias,
    const __nv_bfloat16* __restrict__ Xhi, const __nv_bfloat16* __restrict__ Xlo,
    float* __restrict__ Y, int M, long xStride, long yStride,
    const float* __restrict__ gq, const float* __restrict__ gk)
{
    int b  = blockIdx.z;
    int m0 = blockIdx.y * 128;
    int n0 = blockIdx.x * 128;
    const __nv_bfloat16* XhiB = Xhi + (long)b * xStride;
    const __nv_bfloat16* XloB = Xlo + (long)b * xStride;

    __shared__ __align__(16) __nv_bfloat16 sA[2][2][128 * ASTR];
    __shared__ __align__(16) __nv_bfloat16 sB[2][2][16 * 136];
    __shared__ float sg[8][132];

    int tid  = threadIdx.x;
    int warp = tid >> 5, lane = tid & 31;
    int wm = warp >> 2, wn = warp & 3;
    int g = lane >> 2, t = lane & 3;

    float acc[4][4][4];
    #pragma unroll
    for (int mi = 0; mi < 4; mi++)
        #pragma unroll
        for (int ni = 0; ni < 4; ni++)
            #pragma unroll
            for (int r = 0; r < 4; r++) acc[mi][ni][r] = 0.f;

    auto loadStage = [&](int step, int s) {
        int k0 = step * 16;
        {
            int row = tid >> 1, half = tid & 1;
            int gm = m0 + row;
            __nv_bfloat16* dhi = &sA[s][0][row * ASTR + half * 8];
            __nv_bfloat16* dlo = &sA[s][1][row * ASTR + half * 8];
            if (gm < M) {
                cp16(dhi, Whi + gm * 256 + k0 + half * 8);
                cp16(dlo, Wlo + gm * 256 + k0 + half * 8);
            } else {
                *reinterpret_cast<uint4*>(dhi) = make_uint4(0,0,0,0);
                *reinterpret_cast<uint4*>(dlo) = make_uint4(0,0,0,0);
            }
        }
        {
            int row = tid >> 4, seg = tid & 15;
            cp16(&sB[s][0][row * 136 + seg * 8], XhiB + (long)(k0 + row) * N_ + n0 + seg * 8);
            cp16(&sB[s][1][row * 136 + seg * 8], XloB + (long)(k0 + row) * N_ + n0 + seg * 8);
        }
        cp_commit();
    };

    loadStage(0, 0);
    for (int step = 0; step < 16; step++) {
        int s = step & 1;
        if (step < 15) {
            loadStage(step + 1, s ^ 1);
            asm volatile("cp.async.wait_group 1;");
        } else {
            asm volatile("cp.async.wait_group 0;");
        }
        __syncthreads();

        uint32_t afr[2][4][4];
        #pragma unroll
        for (int v = 0; v < 2; v++)
            #pragma unroll
            for (int mi = 0; mi < 4; mi++) {
                const __nv_bfloat16* p = &sA[s][v][(wm * 64 + mi * 16 + (lane & 15)) * ASTR] + ((lane >> 4) & 1) * 8;
                ldsm_x4(afr[v][mi], p);
            }
        uint32_t bfr[2][4][2];
        #pragma unroll
        for (int v = 0; v < 2; v++)
            #pragma unroll
            for (int ni = 0; ni < 4; ni++) {
                const __nv_bfloat16* p = &sB[s][v][(lane & 15) * 136 + wn * 32 + ni * 8];
                ldsm_x2t(bfr[v][ni], p);
            }
        #pragma unroll
        for (int mi = 0; mi < 4; mi++)
            #pragma unroll
            for (int ni = 0; ni < 4; ni++) {
                mma16816(acc[mi][ni], afr[0][mi], bfr[0][ni]);
                mma16816(acc[mi][ni], afr[0][mi], bfr[1][ni]);
                mma16816(acc[mi][ni], afr[1][mi], bfr[0][ni]);
            }
        __syncthreads();
    }

    float* Yb = Y + (long)b * yStride;
    #pragma unroll
    for (int mi = 0; mi < 4; mi++) {
        int r0 = m0 + wm * 64 + mi * 16 + g;
        int r1 = r0 + 8;
        #pragma unroll
        for (int ni = 0; ni < 4; ni++) {
            int col = n0 + wn * 32 + ni * 8 + 2 * t;
            if (r0 < M) {
                float bv = bias[r0];
                Yb[(long)r0 * N_ + col]     = acc[mi][ni][0] + bv;
                Yb[(long)r0 * N_ + col + 1] = acc[mi][ni][1] + bv;
            }
            if (r1 < M) {
                float bv = bias[r1];
                Yb[(long)r1 * N_ + col]     = acc[mi][ni][2] + bv;
                Yb[(long)r1 * N_ + col + 1] = acc[mi][ni][3] + bv;
            }
        }
    }

    // fused gate softmax: only gemm1's m0==768 blocks (rows 768-775 live in wm==0, mi==0)
    if (gq != nullptr && m0 == 768) {
        if (wm == 0) {
            float bv = bias[768 + g];
            #pragma unroll
            for (int ni = 0; ni < 4; ni++) {
                int col = wn * 32 + ni * 8 + 2 * t;
                sg[g][col]     = acc[0][ni][0] + bv;
                sg[g][col + 1] = acc[0][ni][1] + bv;
            }
        }
        __syncthreads();
        if (tid < 128) {
            int n = n0 + tid;
            float lq[4], lk[4];
            #pragma unroll
            for (int r = 0; r < 4; r++) {
                lq[r] = sg[r][tid]     + gq[(b * R_ + r) * N_ + n];
                lk[r] = sg[4 + r][tid] + gk[(b * R_ + r) * N_ + n];
            }
            float mq = fmaxf(fmaxf(lq[0], lq[1]), fmaxf(lq[2], lq[3]));
            float s2 = 0.f;
            #pragma unroll
            for (int r = 0; r < 4; r++) s2 += __expf(lq[r] - mq);
            g_sq[b * N_ + n] = __expf(lq[0] - mq) / s2;
            float mk = fmaxf(fmaxf(lk[0], lk[1]), fmaxf(lk[2], lk[3]));
            s2 = 0.f;
            #pragma unroll
            for (int r = 0; r < 4; r++) s2 += __expf(lk[r] - mk);
            g_sk[b * N_ + n] = __expf(lk[0] - mk) / s2;
        }
    }
}

// ---------------- wide elementwise convert ----------------
__global__ __launch_bounds__(256) void convert_kernel() {
    int row = blockIdx.x;        // 0..767
    int b   = blockIdx.y;
    int n   = threadIdx.x * 4;
    const float QMUL = SCALE * LOG2E;

    float4 v = *reinterpret_cast<const float4*>(g_proj + ((long)b * MTOT + row) * N_ + n);
    uint2 outp;
    if (row < 256) {
        float4 s = *reinterpret_cast<const float4*>(g_sq + b * N_ + n);
        outp.x = packbf(v.x * s.x * QMUL, v.y * s.y * QMUL);
        outp.y = packbf(v.z * s.z * QMUL, v.w * s.w * QMUL);
        *reinterpret_cast<uint2*>(g_qB + ((long)b * C_ + row) * N_ + n) = outp;
    } else if (row < 512) {
        float4 s = *reinterpret_cast<const float4*>(g_sk + b * N_ + n);
        outp.x = packbf(v.x * s.x, v.y * s.y);
        outp.y = packbf(v.z * s.z, v.w * s.w);
        *reinterpret_cast<uint2*>(g_kB + ((long)b * C_ + row - 256) * N_ + n) = outp;
    } else {
        outp.x = packbf(v.x, v.y);
        outp.y = packbf(v.z, v.w);
        *reinterpret_cast<uint2*>(g_vB + ((long)b * C_ + row - 512) * N_ + n) = outp;
    }
}

// ---------------- flash attention: bf16x2 exp + ones-MMA row sums ----------------
#define QSTR 136
#define KSTR 72
__global__ __launch_bounds__(256) void attn_kernel() {
    int b = blockIdx.z, h = blockIdx.y;
    int n0 = blockIdx.x * 128;
    const __nv_bfloat16* qBp = g_qB + ((long)b * C_ + h * HD) * N_;
    const __nv_bfloat16* kBp = g_kB + ((long)b * C_ + h * HD) * N_;
    const __nv_bfloat16* vBp = g_vB + ((long)b * C_ + h * HD) * N_;

    __shared__ __align__(16) __nv_bfloat16 qsm[32 * QSTR];       // [d][q]
    __shared__ __align__(16) __nv_bfloat16 ksm[2][32 * KSTR];    // [stage][d][key]
    __shared__ __align__(16) __nv_bfloat16 vsm[2][32 * KSTR];
    __shared__ float osm[32][130];

    int tid = threadIdx.x;
    int w = tid >> 5, lane = tid & 31;
    int g = lane >> 2, t = lane & 3;

    auto loadKV = [&](int m0, int s) {
        int row = tid >> 3, seg = tid & 7;
        cp16(&ksm[s][row * KSTR + seg * 8], kBp + (long)row * N_ + m0 + seg * 8);
        cp16(&vsm[s][row * KSTR + seg * 8], vBp + (long)row * N_ + m0 + seg * 8);
        cp_commit();
    };

    loadKV(0, 0);

    #pragma unroll
    for (int c = tid; c < 512; c += 256) {
        int row = c >> 4, seg = c & 15;
        reinterpret_cast<uint4*>(qsm + row * QSTR)[seg] =
            reinterpret_cast<const uint4*>(qBp + (long)row * N_ + n0)[seg];
    }
    __syncthreads();

    uint32_t aq[2][4];
    #pragma unroll
    for (int ku = 0; ku < 2; ku++) {
        int d = ku * 16 + ((lane >> 4) & 1) * 8 + (lane & 7);
        int col = w * 16 + ((lane >> 3) & 1) * 8;
        ldsm_x4t(aq[ku], qsm + d * QSTR + col);
    }

    float oacc[4][4];
    #pragma unroll
    for (int nd = 0; nd < 4; nd++)
        #pragma unroll
        for (int r = 0; r < 4; r++) oacc[nd][r] = 0.f;
    float lacc[4] = {0.f, 0.f, 0.f, 0.f};
    uint32_t bones[2];
    bones[0] = 0x3F803F80u; bones[1] = 0x3F803F80u;   // bf16 1.0 x2

    for (int it = 0; it < 16; it++) {
        int s = it & 1;
        if (it < 15) {
            loadKV((it + 1) * 64, s ^ 1);
            asm volatile("cp.async.wait_group 1;");
        } else {
            asm volatile("cp.async.wait_group 0;");
        }
        __syncthreads();

        float sS[8][4];
        #pragma unroll
        for (int ni = 0; ni < 8; ni++) {
            #pragma unroll
            for (int r = 0; r < 4; r++) sS[ni][r] = 0.f;
            #pragma unroll
            for (int ku = 0; ku < 2; ku++) {
                uint32_t bk[2];
                ldsm_x2t(bk, &ksm[s][(ku * 16 + (lane & 15)) * KSTR + ni * 8]);
                mma16816(sS[ni], aq[ku], bk);
            }
        }

        // P = 2^S in packed bf16x2; row sums via ones-MMA (exact match with PV operand)
        #pragma unroll
        for (int u = 0; u < 4; u++) {
            uint32_t ap[4];
            ap[0] = ex2_bf16x2(cvt2bf(sS[2*u][1],   sS[2*u][0]));
            ap[1] = ex2_bf16x2(cvt2bf(sS[2*u][3],   sS[2*u][2]));
            ap[2] = ex2_bf16x2(cvt2bf(sS[2*u+1][1], sS[2*u+1][0]));
            ap[3] = ex2_bf16x2(cvt2bf(sS[2*u+1][3], sS[2*u+1][2]));
            mma16816(lacc, ap, bones);
            #pragma unroll
            for (int nd = 0; nd < 4; nd++) {
                uint32_t bv[2];
                ldsm_x2(bv, &vsm[s][(nd * 8 + (lane & 7)) * KSTR + u * 16 + ((lane >> 3) & 1) * 8]);
                mma16816(oacc[nd], ap, bv);
            }
        }
        __syncthreads();
    }

    // lacc[0] = full row sum for q-row g, lacc[2] for row g+8 (no shuffle needed)
    float inv0 = 1.f / lacc[0], inv1 = 1.f / lacc[2];

    #pragma unroll
    for (int nd = 0; nd < 4; nd++) {
        osm[nd * 8 + 2 * t][w * 16 + g]         = oacc[nd][0] * inv0;
        osm[nd * 8 + 2 * t + 1][w * 16 + g]     = oacc[nd][1] * inv0;
        osm[nd * 8 + 2 * t][w * 16 + g + 8]     = oacc[nd][2] * inv1;
        osm[nd * 8 + 2 * t + 1][w * 16 + g + 8] = oacc[nd][3] * inv1;
    }
    __syncthreads();

    const float* vfull = g_proj + ((long)b * MTOT + 512 + h * HD) * N_ + n0;
    int n = tid & 127;
    float sqv = g_sq[b * N_ + n0 + n];
    #pragma unroll
    for (int d = tid >> 7; d < HD; d += 2) {
        float gated = sqv * osm[d][n] + (1.f - sqv) * vfull[(long)d * N_ + n];
        __nv_bfloat16 hi, lo; split_bf(gated, hi, lo);
        long gidx = ((long)b * C_ + h * HD + d) * N_ + n0 + n;
        g_ghi[gidx] = hi; g_glo[gidx] = lo;
    }
}

// ---------------- launch ----------------
extern "C" void kernel_launch(void* const* d_in, const int* in_sizes, int n_in,
                              void* d_out, int out_size) {
    const float* x   = (const float*)d_in[0];
    const float* gq  = (const float*)d_in[1];
    const float* gk  = (const float*)d_in[2];
    const float* Wsq = (const float*)d_in[3];
    const float* bsq = (const float*)d_in[4];
    const float* Wsk = (const float*)d_in[5];
    const float* bsk = (const float*)d_in[6];
    const float* Wq  = (const float*)d_in[7];
    const float* bq  = (const float*)d_in[8];
    const float* Wk  = (const float*)d_in[9];
    const float* bk  = (const float*)d_in[10];
    const float* Wv  = (const float*)d_in[11];
    const float* bv  = (const float*)d_in[12];
    const float* Wp  = (const float*)d_in[13];
    const float* bp  = (const float*)d_in[14];
    float* out = (float*)d_out;

    void *whi, *wlo, *ball, *wphi, *wplo, *xhi, *xlo, *proj, *ghi, *glo;
    cudaGetSymbolAddress(&whi,  g_whi);
    cudaGetSymbolAddress(&wlo,  g_wlo);
    cudaGetSymbolAddress(&ball, g_ball);
    cudaGetSymbolAddress(&wphi, g_wphi);
    cudaGetSymbolAddress(&wplo, g_wplo);
    cudaGetSymbolAddress(&xhi,  g_xhi);
    cudaGetSymbolAddress(&xlo,  g_xlo);
    cudaGetSymbolAddress(&proj, g_proj);
    cudaGetSymbolAddress(&ghi,  g_ghi);
    cudaGetSymbolAddress(&glo,  g_glo);

    assemble_split_kernel<<<MTOT + C_, 256>>>(Wq, bq, Wk, bk, Wv, bv, Wsq, bsq, Wsk, bsk, Wp);
    xsplit_kernel<<<(B_ * C_ * N_) / 1024, 256>>>(x);

    {   // proj = Wall @ x  (bf16x3), gates fused into m0==768 blocks' epilogue
        dim3 g(N_ / 128, (MTOT + 127) / 128, B_);
        gemm3x_kernel<<<g, 256>>>((const __nv_bfloat16*)whi, (const __nv_bfloat16*)wlo,
                                  (const float*)ball,
                                  (const __nv_bfloat16*)xhi, (const __nv_bfloat16*)xlo,
                                  (float*)proj, MTOT, (long)C_ * N_, (long)MTOT * N_,
                                  gq, gk);
    }

    {   // wide elementwise convert (gates already written by gemm1)
        dim3 g(768, B_);
        convert_kernel<<<g, 256>>>();
    }

    {   // attention + blend
        dim3 g(N_ / 128, NH, B_);
        attn_kernel<<<g, 256>>>();
    }

    {   // out = Wp @ gated  (bf16x3)
        dim3 g(N_ / 128, C_ / 128, B_);
        gemm3x_kernel<<<g, 256>>>((const __nv_bfloat16*)wphi, (const __nv_bfloat16*)wplo,
                                  bp,
                                  (const __nv_bfloat16*)ghi, (const __nv_bfloat16*)glo,
                                  out, C_, (long)C_ * N_, (long)C_ * N_,
                                  nullptr, nullptr);
    }
}

// round 10
// speedup vs baseline: 1.7356x; 1.3698x over previous
#include <cuda_runtime.h>
#include <cuda_bf16.h>
#include <cuda_fp16.h>
#include <cstdint>

#define B_    8
#define C_    256
#define N_    1024
#define NH    8
#define HD    32
#define R_    4
#define MTOT  776
#define SCALE 0.17677669529663689f
#define LOG2E 1.4426950408889634f

// ---------------- scratch ----------------
__device__ float g_proj[B_ * MTOT * N_];
__device__ float g_sq[B_ * N_];
__device__ float g_sk[B_ * N_];
__device__ float g_ball[MTOT];
__device__ __half g_wh[MTOT * C_];            // stacked W (fp16)
__device__ __half g_wph[C_ * C_];             // Wp (fp16)
__device__ __half g_xh[B_ * C_ * N_];         // x (fp16)
__device__ __nv_bfloat16 g_qB[B_ * C_ * N_];  // gated*SCALE*LOG2E (bf16, attn)
__device__ __nv_bfloat16 g_kB[B_ * C_ * N_];  // gated
__device__ __nv_bfloat16 g_vB[B_ * C_ * N_];
__device__ __half g_gh[B_ * C_ * N_];         // gated output (fp16, gemm2 input)

// ---------------- ptx helpers ----------------
__device__ __forceinline__ void cp16(void* d, const void* s) {
    uint32_t ds = (uint32_t)__cvta_generic_to_shared(d);
    asm volatile("cp.async.cg.shared.global [%0], [%1], 16;" :: "r"(ds), "l"(s));
}
__device__ __forceinline__ void cp_commit() { asm volatile("cp.async.commit_group;"); }

__device__ __forceinline__ void ldsm_x4(uint32_t (&r)[4], const void* p) {
    uint32_t a = (uint32_t)__cvta_generic_to_shared(p);
    asm volatile("ldmatrix.sync.aligned.m8n8.x4.shared.b16 {%0,%1,%2,%3},[%4];"
                 : "=r"(r[0]), "=r"(r[1]), "=r"(r[2]), "=r"(r[3]) : "r"(a));
}
__device__ __forceinline__ void ldsm_x4t(uint32_t (&r)[4], const void* p) {
    uint32_t a = (uint32_t)__cvta_generic_to_shared(p);
    asm volatile("ldmatrix.sync.aligned.m8n8.x4.trans.shared.b16 {%0,%1,%2,%3},[%4];"
                 : "=r"(r[0]), "=r"(r[1]), "=r"(r[2]), "=r"(r[3]) : "r"(a));
}
__device__ __forceinline__ void ldsm_x2(uint32_t (&r)[2], const void* p) {
    uint32_t a = (uint32_t)__cvta_generic_to_shared(p);
    asm volatile("ldmatrix.sync.aligned.m8n8.x2.shared.b16 {%0,%1},[%2];"
                 : "=r"(r[0]), "=r"(r[1]) : "r"(a));
}
__device__ __forceinline__ void ldsm_x2t(uint32_t (&r)[2], const void* p) {
    uint32_t a = (uint32_t)__cvta_generic_to_shared(p);
    asm volatile("ldmatrix.sync.aligned.m8n8.x2.trans.shared.b16 {%0,%1},[%2];"
                 : "=r"(r[0]), "=r"(r[1]) : "r"(a));
}
// bf16 mma (attention)
__device__ __forceinline__ void mma16816(float (&d)[4], const uint32_t (&a)[4], const uint32_t (&b)[2]) {
    asm volatile(
        "mma.sync.aligned.m16n8k16.row.col.f32.bf16.bf16.f32 "
        "{%0,%1,%2,%3},{%4,%5,%6,%7},{%8,%9},{%0,%1,%2,%3};"
        : "+f"(d[0]), "+f"(d[1]), "+f"(d[2]), "+f"(d[3])
        : "r"(a[0]), "r"(a[1]), "r"(a[2]), "r"(a[3]), "r"(b[0]), "r"(b[1]));
}
// fp16 mma (projection GEMMs)
__device__ __forceinline__ void mmah16816(float (&d)[4], const uint32_t (&a)[4], const uint32_t (&b)[2]) {
    asm volatile(
        "mma.sync.aligned.m16n8k16.row.col.f32.f16.f16.f32 "
        "{%0,%1,%2,%3},{%4,%5,%6,%7},{%8,%9},{%0,%1,%2,%3};"
        : "+f"(d[0]), "+f"(d[1]), "+f"(d[2]), "+f"(d[3])
        : "r"(a[0]), "r"(a[1]), "r"(a[2]), "r"(a[3]), "r"(b[0]), "r"(b[1]));
}
__device__ __forceinline__ uint32_t packbf(float lo, float hi) {
    __nv_bfloat162 t = __floats2bfloat162_rn(lo, hi);
    return *reinterpret_cast<uint32_t*>(&t);
}
__device__ __forceinline__ uint32_t cvt2bf(float hi, float lo) {
    uint32_t y; asm("cvt.rn.bf16x2.f32 %0, %1, %2;" : "=r"(y) : "f"(hi), "f"(lo)); return y;
}
__device__ __forceinline__ uint32_t ex2_bf16x2(uint32_t x) {
    uint32_t y; asm("ex2.approx.ftz.bf16x2 %0, %1;" : "=r"(y) : "r"(x)); return y;
}

// ---------------- assemble weights -> fp16 ----------------
__global__ void assemble_kernel(
    const float* __restrict__ Wq, const float* __restrict__ bq,
    const float* __restrict__ Wk, const float* __restrict__ bk,
    const float* __restrict__ Wv, const float* __restrict__ bv,
    const float* __restrict__ Wsq, const float* __restrict__ bsq,
    const float* __restrict__ Wsk, const float* __restrict__ bsk,
    const float* __restrict__ Wp)
{
    int o = blockIdx.x;
    int k = threadIdx.x;
    if (o < MTOT) {
        const float* src; const float* bs; int r;
        if (o < 256)      { src = Wq  + o * 256;       bs = bq;  r = o; }
        else if (o < 512) { src = Wk  + (o-256) * 256; bs = bk;  r = o - 256; }
        else if (o < 768) { src = Wv  + (o-512) * 256; bs = bv;  r = o - 512; }
        else if (o < 772) { src = Wsq + (o-768) * 256; bs = bsq; r = o - 768; }
        else              { src = Wsk + (o-772) * 256; bs = bsk; r = o - 772; }
        g_wh[o * 256 + k] = __float2half_rn(src[k]);
        if (k == 0) g_ball[o] = bs[r];
    } else {
        int r = o - MTOT;
        g_wph[r * 256 + k] = __float2half_rn(Wp[r * 256 + k]);
    }
}

// ---------------- x -> fp16 (float4) ----------------
__global__ void xcvt_kernel(const float* __restrict__ x) {
    int i = (blockIdx.x * 256 + threadIdx.x) * 4;
    float4 v = *reinterpret_cast<const float4*>(x + i);
    __half2 p0 = __floats2half2_rn(v.x, v.y);
    __half2 p1 = __floats2half2_rn(v.z, v.w);
    uint2 o;
    o.x = *reinterpret_cast<uint32_t*>(&p0);
    o.y = *reinterpret_cast<uint32_t*>(&p1);
    *reinterpret_cast<uint2*>(g_xh + i) = o;
}

// ---------------- fp16 GEMM, 2-stage cp.async, padded A, fused gates ----------------
#define ASTR 24
__global__ __launch_bounds__(256) void gemmh_kernel(
    const __half* __restrict__ W, const float* __restrict__ bias,
    const __half* __restrict__ X, float* __restrict__ Y,
    int M, long xStride, long yStride,
    const float* __restrict__ gq, const float* __restrict__ gk)
{
    int b  = blockIdx.z;
    int m0 = blockIdx.y * 128;
    int n0 = blockIdx.x * 128;
    const __half* XB = X + (long)b * xStride;

    __shared__ __align__(16) __half sA[2][128 * ASTR];
    __shared__ __align__(16) __half sB[2][16 * 136];
    __shared__ float sg[8][132];

    int tid  = threadIdx.x;
    int warp = tid >> 5, lane = tid & 31;
    int wm = warp >> 2, wn = warp & 3;
    int g = lane >> 2, t = lane & 3;

    float acc[4][4][4];
    #pragma unroll
    for (int mi = 0; mi < 4; mi++)
        #pragma unroll
        for (int ni = 0; ni < 4; ni++)
            #pragma unroll
            for (int r = 0; r < 4; r++) acc[mi][ni][r] = 0.f;

    auto loadStage = [&](int step, int s) {
        int k0 = step * 16;
        {   // A: 128 rows x 32B = 256 chunks
            int row = tid >> 1, half = tid & 1;
            int gm = m0 + row;
            __half* d = &sA[s][row * ASTR + half * 8];
            if (gm < M) cp16(d, W + gm * 256 + k0 + half * 8);
            else        *reinterpret_cast<uint4*>(d) = make_uint4(0,0,0,0);
        }
        {   // B: 16 rows x 256B = 256 chunks
            int row = tid >> 4, seg = tid & 15;
            cp16(&sB[s][row * 136 + seg * 8], XB + (long)(k0 + row) * N_ + n0 + seg * 8);
        }
        cp_commit();
    };

    loadStage(0, 0);
    for (int step = 0; step < 16; step++) {
        int s = step & 1;
        if (step < 15) {
            loadStage(step + 1, s ^ 1);
            asm volatile("cp.async.wait_group 1;");
        } else {
            asm volatile("cp.async.wait_group 0;");
        }
        __syncthreads();

        uint32_t afr[4][4];
        #pragma unroll
        for (int mi = 0; mi < 4; mi++) {
            const __half* p = &sA[s][(wm * 64 + mi * 16 + (lane & 15)) * ASTR] + ((lane >> 4) & 1) * 8;
            ldsm_x4(afr[mi], p);
        }
        uint32_t bfr[4][2];
        #pragma unroll
        for (int ni = 0; ni < 4; ni++) {
            const __half* p = &sB[s][(lane & 15) * 136 + wn * 32 + ni * 8];
            ldsm_x2t(bfr[ni], p);
        }
        #pragma unroll
        for (int mi = 0; mi < 4; mi++)
            #pragma unroll
            for (int ni = 0; ni < 4; ni++)
                mmah16816(acc[mi][ni], afr[mi], bfr[ni]);
        __syncthreads();
    }

    float* Yb = Y + (long)b * yStride;
    #pragma unroll
    for (int mi = 0; mi < 4; mi++) {
        int r0 = m0 + wm * 64 + mi * 16 + g;
        int r1 = r0 + 8;
        #pragma unroll
        for (int ni = 0; ni < 4; ni++) {
            int col = n0 + wn * 32 + ni * 8 + 2 * t;
            if (r0 < M) {
                float bv = bias[r0];
                Yb[(long)r0 * N_ + col]     = acc[mi][ni][0] + bv;
                Yb[(long)r0 * N_ + col + 1] = acc[mi][ni][1] + bv;
            }
            if (r1 < M) {
                float bv = bias[r1];
                Yb[(long)r1 * N_ + col]     = acc[mi][ni][2] + bv;
                Yb[(long)r1 * N_ + col + 1] = acc[mi][ni][3] + bv;
            }
        }
    }

    // fused gate softmax: gemm1's m0==768 blocks only
    if (gq != nullptr && m0 == 768) {
        if (wm == 0) {
            float bv = bias[768 + g];
            #pragma unroll
            for (int ni = 0; ni < 4; ni++) {
                int col = wn * 32 + ni * 8 + 2 * t;
                sg[g][col]     = acc[0][ni][0] + bv;
                sg[g][col + 1] = acc[0][ni][1] + bv;
            }
        }
        __syncthreads();
        if (tid < 128) {
            int n = n0 + tid;
            float lq[4], lk[4];
            #pragma unroll
            for (int r = 0; r < 4; r++) {
                lq[r] = sg[r][tid]     + gq[(b * R_ + r) * N_ + n];
                lk[r] = sg[4 + r][tid] + gk[(b * R_ + r) * N_ + n];
            }
            float mq = fmaxf(fmaxf(lq[0], lq[1]), fmaxf(lq[2], lq[3]));
            float s2 = 0.f;
            #pragma unroll
            for (int r = 0; r < 4; r++) s2 += __expf(lq[r] - mq);
            g_sq[b * N_ + n] = __expf(lq[0] - mq) / s2;
            float mk = fmaxf(fmaxf(lk[0], lk[1]), fmaxf(lk[2], lk[3]));
            s2 = 0.f;
            #pragma unroll
            for (int r = 0; r < 4; r++) s2 += __expf(lk[r] - mk);
            g_sk[b * N_ + n] = __expf(lk[0] - mk) / s2;
        }
    }
}

// ---------------- wide elementwise convert (proj fp32 -> gated bf16 q/k/v) ----------------
__global__ __launch_bounds__(256) void convert_kernel() {
    int row = blockIdx.x;        // 0..767
    int b   = blockIdx.y;
    int n   = threadIdx.x * 4;
    const float QMUL = SCALE * LOG2E;

    float4 v = *reinterpret_cast<const float4*>(g_proj + ((long)b * MTOT + row) * N_ + n);
    uint2 outp;
    if (row < 256) {
        float4 s = *reinterpret_cast<const float4*>(g_sq + b * N_ + n);
        outp.x = packbf(v.x * s.x * QMUL, v.y * s.y * QMUL);
        outp.y = packbf(v.z * s.z * QMUL, v.w * s.w * QMUL);
        *reinterpret_cast<uint2*>(g_qB + ((long)b * C_ + row) * N_ + n) = outp;
    } else if (row < 512) {
        float4 s = *reinterpret_cast<const float4*>(g_sk + b * N_ + n);
        outp.x = packbf(v.x * s.x, v.y * s.y);
        outp.y = packbf(v.z * s.z, v.w * s.w);
        *reinterpret_cast<uint2*>(g_kB + ((long)b * C_ + row - 256) * N_ + n) = outp;
    } else {
        outp.x = packbf(v.x, v.y);
        outp.y = packbf(v.z, v.w);
        *reinterpret_cast<uint2*>(g_vB + ((long)b * C_ + row - 512) * N_ + n) = outp;
    }
}

// ---------------- flash attention: bf16x2 exp + ones-MMA row sums ----------------
#define QSTR 136
#define KSTR 72
__global__ __launch_bounds__(256) void attn_kernel() {
    int b = blockIdx.z, h = blockIdx.y;
    int n0 = blockIdx.x * 128;
    const __nv_bfloat16* qBp = g_qB + ((long)b * C_ + h * HD) * N_;
    const __nv_bfloat16* kBp = g_kB + ((long)b * C_ + h * HD) * N_;
    const __nv_bfloat16* vBp = g_vB + ((long)b * C_ + h * HD) * N_;

    __shared__ __align__(16) __nv_bfloat16 qsm[32 * QSTR];       // [d][q]
    __shared__ __align__(16) __nv_bfloat16 ksm[2][32 * KSTR];    // [stage][d][key]
    __shared__ __align__(16) __nv_bfloat16 vsm[2][32 * KSTR];
    __shared__ float osm[32][130];

    int tid = threadIdx.x;
    int w = tid >> 5, lane = tid & 31;
    int g = lane >> 2, t = lane & 3;

    auto loadKV = [&](int m0, int s) {
        int row = tid >> 3, seg = tid & 7;
        cp16(&ksm[s][row * KSTR + seg * 8], kBp + (long)row * N_ + m0 + seg * 8);
        cp16(&vsm[s][row * KSTR + seg * 8], vBp + (long)row * N_ + m0 + seg * 8);
        cp_commit();
    };

    loadKV(0, 0);

    #pragma unroll
    for (int c = tid; c < 512; c += 256) {
        int row = c >> 4, seg = c & 15;
        reinterpret_cast<uint4*>(qsm + row * QSTR)[seg] =
            reinterpret_cast<const uint4*>(qBp + (long)row * N_ + n0)[seg];
    }
    __syncthreads();

    uint32_t aq[2][4];
    #pragma unroll
    for (int ku = 0; ku < 2; ku++) {
        int d = ku * 16 + ((lane >> 4) & 1) * 8 + (lane & 7);
        int col = w * 16 + ((lane >> 3) & 1) * 8;
        ldsm_x4t(aq[ku], qsm + d * QSTR + col);
    }

    float oacc[4][4];
    #pragma unroll
    for (int nd = 0; nd < 4; nd++)
        #pragma unroll
        for (int r = 0; r < 4; r++) oacc[nd][r] = 0.f;
    float lacc[4] = {0.f, 0.f, 0.f, 0.f};
    uint32_t bones[2];
    bones[0] = 0x3F803F80u; bones[1] = 0x3F803F80u;   // bf16 1.0 x2

    for (int it = 0; it < 16; it++) {
        int s = it & 1;
        if (it < 15) {
            loadKV((it + 1) * 64, s ^ 1);
            asm volatile("cp.async.wait_group 1;");
        } else {
            asm volatile("cp.async.wait_group 0;");
        }
        __syncthreads();

        float sS[8][4];
        #pragma unroll
        for (int ni = 0; ni < 8; ni++) {
            #pragma unroll
            for (int r = 0; r < 4; r++) sS[ni][r] = 0.f;
            #pragma unroll
            for (int ku = 0; ku < 2; ku++) {
                uint32_t bk[2];
                ldsm_x2t(bk, &ksm[s][(ku * 16 + (lane & 15)) * KSTR + ni * 8]);
                mma16816(sS[ni], aq[ku], bk);
            }
        }

        #pragma unroll
        for (int u = 0; u < 4; u++) {
            uint32_t ap[4];
            ap[0] = ex2_bf16x2(cvt2bf(sS[2*u][1],   sS[2*u][0]));
            ap[1] = ex2_bf16x2(cvt2bf(sS[2*u][3],   sS[2*u][2]));
            ap[2] = ex2_bf16x2(cvt2bf(sS[2*u+1][1], sS[2*u+1][0]));
            ap[3] = ex2_bf16x2(cvt2bf(sS[2*u+1][3], sS[2*u+1][2]));
            mma16816(lacc, ap, bones);
            #pragma unroll
            for (int nd = 0; nd < 4; nd++) {
                uint32_t bv[2];
                ldsm_x2(bv, &vsm[s][(nd * 8 + (lane & 7)) * KSTR + u * 16 + ((lane >> 3) & 1) * 8]);
                mma16816(oacc[nd], ap, bv);
            }
        }
        __syncthreads();
    }

    float inv0 = 1.f / lacc[0], inv1 = 1.f / lacc[2];

    #pragma unroll
    for (int nd = 0; nd < 4; nd++) {
        osm[nd * 8 + 2 * t][w * 16 + g]         = oacc[nd][0] * inv0;
        osm[nd * 8 + 2 * t + 1][w * 16 + g]     = oacc[nd][1] * inv0;
        osm[nd * 8 + 2 * t][w * 16 + g + 8]     = oacc[nd][2] * inv1;
        osm[nd * 8 + 2 * t + 1][w * 16 + g + 8] = oacc[nd][3] * inv1;
    }
    __syncthreads();

    const float* vfull = g_proj + ((long)b * MTOT + 512 + h * HD) * N_ + n0;
    int n = tid & 127;
    float sqv = g_sq[b * N_ + n0 + n];
    #pragma unroll
    for (int d = tid >> 7; d < HD; d += 2) {
        float gated = sqv * osm[d][n] + (1.f - sqv) * vfull[(long)d * N_ + n];
        g_gh[((long)b * C_ + h * HD + d) * N_ + n0 + n] = __float2half_rn(gated);
    }
}

// ---------------- launch ----------------
extern "C" void kernel_launch(void* const* d_in, const int* in_sizes, int n_in,
                              void* d_out, int out_size) {
    const float* x   = (const float*)d_in[0];
    const float* gq  = (const float*)d_in[1];
    const float* gk  = (const float*)d_in[2];
    const float* Wsq = (const float*)d_in[3];
    const float* bsq = (const float*)d_in[4];
    const float* Wsk = (const float*)d_in[5];
    const float* bsk = (const float*)d_in[6];
    const float* Wq  = (const float*)d_in[7];
    const float* bq  = (const float*)d_in[8];
    const float* Wk  = (const float*)d_in[9];
    const float* bk  = (const float*)d_in[10];
    const float* Wv  = (const float*)d_in[11];
    const float* bv  = (const float*)d_in[12];
    const float* Wp  = (const float*)d_in[13];
    const float* bp  = (const float*)d_in[14];
    float* out = (float*)d_out;

    void *wh, *ball, *wph, *xh, *proj, *gh;
    cudaGetSymbolAddress(&wh,   g_wh);
    cudaGetSymbolAddress(&ball, g_ball);
    cudaGetSymbolAddress(&wph,  g_wph);
    cudaGetSymbolAddress(&xh,   g_xh);
    cudaGetSymbolAddress(&proj, g_proj);
    cudaGetSymbolAddress(&gh,   g_gh);

    assemble_kernel<<<MTOT + C_, 256>>>(Wq, bq, Wk, bk, Wv, bv, Wsq, bsq, Wsk, bsk, Wp);
    xcvt_kernel<<<(B_ * C_ * N_) / 1024, 256>>>(x);

    {   // proj = Wall @ x  (fp16), gates fused into m0==768 blocks
        dim3 g(N_ / 128, (MTOT + 127) / 128, B_);
        gemmh_kernel<<<g, 256>>>((const __half*)wh, (const float*)ball,
                                 (const __half*)xh, (float*)proj,
                                 MTOT, (long)C_ * N_, (long)MTOT * N_,
                                 gq, gk);
    }

    {   // wide elementwise convert
        dim3 g(768, B_);
        convert_kernel<<<g, 256>>>();
    }

    {   // attention + blend -> fp16 gated
        dim3 g(N_ / 128, NH, B_);
        attn_kernel<<<g, 256>>>();
    }

    {   // out = Wp @ gated  (fp16)
        dim3 g(N_ / 128, C_ / 128, B_);
        gemmh_kernel<<<g, 256>>>((const __half*)wph, bp,
                                 (const __half*)gh, out,
                                 C_, (long)C_ * N_, (long)C_ * N_,
                                 nullptr, nullptr);
    }
}